// round 14
// baseline (speedup 1.0000x reference)
#include <cuda_runtime.h>
#include <cuda_bf16.h>

// y = D @ x per row, D = blockdiag(1024 x [4x4]) + diag(rem[3]).
// x: (16384, 4099) fp32. Row stride 4099 ≡ 3 (mod 4).
// R13 structure with RPC=16: four sequential static 4-row batches per CTA,
// amortizing the 16-wavefront weight load over 2x more data traffic
// (weights drop from ~18% to ~10% of per-CTA L1 wavefronts).
//  * r pattern {0,3,2,1}: r=0 clean f4; r=2 direct 8B-aligned f2 (no shfl);
//    r=3 full shuffle path (6 shfl, f4 patch);
//    r=1 only 2 shuffles + scalar patch.

#define BS     4
#define GPC    256   // groups per CTA == blockDim.x
#define RPC    16    // rows per CTA (four static batches of 4)

struct W4 { float4 w0, w1, w2, w3; };

__device__ __forceinline__ float4 apply_w(const W4& w,
                                          float x0, float x1, float x2, float x3)
{
    float4 o;
    o.x = w.w0.x*x0 + w.w0.y*x1 + w.w0.z*x2 + w.w0.w*x3;
    o.y = w.w1.x*x0 + w.w1.y*x1 + w.w1.z*x2 + w.w1.w*x3;
    o.z = w.w2.x*x0 + w.w2.y*x1 + w.w2.z*x2 + w.w2.w*x3;
    o.w = w.w3.x*x0 + w.w3.y*x1 + w.w3.z*x2 + w.w3.w*x3;
    return o;
}

// R == 3 row: q at (s-3)+4*lane, p = lane31 patch quad x[(s-3)+128 ..].
__device__ __forceinline__ void process_row_r3(
    float4 q, float4 p, int s, int lane, const W4& w, float* __restrict__ y)
{
    float nx = __shfl_down_sync(0xffffffffu, q.x, 1);
    float ny = __shfl_down_sync(0xffffffffu, q.y, 1);
    float nz = __shfl_down_sync(0xffffffffu, q.z, 1);
    if (lane == 31) { nx = p.x; ny = p.y; nz = p.z; }

    float4 v = apply_w(w, q.w, nx, ny, nz);

    float p1 = __shfl_up_sync(0xffffffffu, v.y, 1);
    float p2 = __shfl_up_sync(0xffffffffu, v.z, 1);
    float p3 = __shfl_up_sync(0xffffffffu, v.w, 1);
    float4 o; o.x = p1; o.y = p2; o.z = p3; o.w = v.x;

    if (lane > 0) {
        __stcs(reinterpret_cast<float4*>(y + (s - 3)) + lane, o);
    } else {
        y[s + 0] = v.x;
    }
    if (lane == 31) {
        y[s + 125] = v.y; y[s + 126] = v.z; y[s + 127] = v.w;
    }
}

// R == 1 row: q at (s-1)+4*lane, px = lane31 scalar patch x[s+127].
__device__ __forceinline__ void process_row_r1(
    float4 q, float px, int s, int lane, const W4& w, float* __restrict__ y)
{
    float nx = __shfl_down_sync(0xffffffffu, q.x, 1);
    if (lane == 31) nx = px;

    float4 v = apply_w(w, q.y, q.z, q.w, nx);

    float p3 = __shfl_up_sync(0xffffffffu, v.w, 1);
    float4 o; o.x = p3; o.y = v.x; o.z = v.y; o.w = v.z;

    if (lane > 0) {
        __stcs(reinterpret_cast<float4*>(y + (s - 1)) + lane, o);
    } else {
        y[s + 0] = v.x; y[s + 1] = v.y; y[s + 2] = v.z;
    }
    if (lane == 31) {
        y[s + 127] = v.w;
    }
}

// One static 4-row batch starting at flat offset s0 (s0 % 4 == 0).
// r per row: {0, 3, 2, 1}.
__device__ __forceinline__ void process_batch4(
    const float* __restrict__ x, float* __restrict__ y,
    int s0, int row_len, int lane, const W4& w)
{
    const float4* a0 = reinterpret_cast<const float4*>(x + s0);
    const float4* a1 = reinterpret_cast<const float4*>(x + s0 +     row_len - 3);
    const float2* a2 = reinterpret_cast<const float2*>(x + s0 + 2 * row_len + 4 * lane);
    const float4* a3 = reinterpret_cast<const float4*>(x + s0 + 3 * row_len - 1);

    // ---- load phase: all rows in flight before compute ----
    float4 q0 = __ldcs(a0 + lane);
    float4 q1 = __ldcs(a1 + lane);
    float2 q2l = __ldcs(a2 + 0);
    float2 q2h = __ldcs(a2 + 1);
    float4 q3 = __ldcs(a3 + lane);
    float4 p1 = {0,0,0,0};
    float  p3x = 0.0f;
    if (lane == 31) {
        p1  = __ldg(a1 + 32);                       // f4 patch (x,y,z used)
        p3x = __ldg(x + s0 + 3 * row_len + 127);    // scalar patch for r=1 row
    }

    // row +0 (r=0): clean float4
    {
        float4 o = apply_w(w, q0.x, q0.y, q0.z, q0.w);
        __stcs(reinterpret_cast<float4*>(y + s0) + lane, o);
    }
    // row +1 (r=3)
    process_row_r3(q1, p1, s0 + row_len, lane, w, y);
    // row +2 (r=2): direct 8B-aligned float2 path
    {
        float4 o = apply_w(w, q2l.x, q2l.y, q2h.x, q2h.y);
        float2* ob = reinterpret_cast<float2*>(y + s0 + 2 * row_len + 4 * lane);
        __stcs(ob + 0, make_float2(o.x, o.y));
        __stcs(ob + 1, make_float2(o.z, o.w));
    }
    // row +3 (r=1)
    process_row_r1(q3, p3x, s0 + 3 * row_len, lane, w, y);
}

__global__ void __launch_bounds__(256, 4) block_apply_vec9_kernel(
    const float* __restrict__ x,
    const float* __restrict__ blocks,
    const float* __restrict__ dr,
    float* __restrict__ y,
    int n_blocks, int rem, int row_len, int total_rows)
{
    const int tid  = threadIdx.x;
    const int lane = tid & 31;
    const int g    = blockIdx.x * GPC + tid;

    W4 w;
    {
        const float4* bp = reinterpret_cast<const float4*>(blocks) + g * BS;
        w.w0 = __ldg(bp + 0); w.w1 = __ldg(bp + 1);
        w.w2 = __ldg(bp + 2); w.w3 = __ldg(bp + 3);
    }

    const int row0 = blockIdx.y * RPC;                    // multiple of 4
    const int warp_col0 = blockIdx.x * (GPC * BS) + (tid & ~31) * BS;

    if (row0 + RPC <= total_rows) {
        int s0 = row0 * row_len + warp_col0;              // s0 % 4 == 0
        #pragma unroll
        for (int b = 0; b < RPC / 4; ++b) {
            process_batch4(x, y, s0, row_len, lane, w);
            s0 += 4 * row_len;
        }
    } else {
        // generic tail rows: scalar per-group path
        for (int row = row0; row < total_rows; ++row) {
            int base = row * row_len + g * BS;
            float4 o = apply_w(w, x[base+0], x[base+1], x[base+2], x[base+3]);
            y[base+0] = o.x; y[base+1] = o.y; y[base+2] = o.z; y[base+3] = o.w;
        }
    }

    // fused remainder duty: last column-CTA handles the diagonal tail
    if (blockIdx.x == gridDim.x - 1) {
        const int colbase = n_blocks * BS;
        const int tail = row_len - colbase;                 // == rem here
        const int row1 = min(row0 + RPC, total_rows);
        const int nrows = row1 - row0;
        const int tot = tail * nrows;
        for (int t = tid; t < tot; t += blockDim.x) {
            int rr = t / tail;
            int k  = t - rr * tail;
            int idx = (row0 + rr) * row_len + colbase + k;
            y[idx] = (k < rem) ? x[idx] * __ldg(dr + k) : 0.0f;
        }
    }
}

// Fallback for general shapes: thread owns a block, scalar path.
__global__ void __launch_bounds__(256) block_apply_simple_kernel(
    const float* __restrict__ x, const float* __restrict__ blocks,
    const float* __restrict__ dr, float* __restrict__ y,
    int n_blocks, int rem, int row_len, int total_rows, int rows_per_cta)
{
    const int b = blockIdx.x * blockDim.x + threadIdx.x;
    int row0 = blockIdx.y * rows_per_cta;
    int row1 = min(row0 + rows_per_cta, total_rows);
    if (b < n_blocks) {
        const float4* bp = reinterpret_cast<const float4*>(blocks) + b * BS;
        W4 w; w.w0 = __ldg(bp+0); w.w1 = __ldg(bp+1);
              w.w2 = __ldg(bp+2); w.w3 = __ldg(bp+3);
        int base = row0 * row_len + b * BS;
        for (int row = row0; row < row1; ++row, base += row_len) {
            float4 o = apply_w(w, x[base+0], x[base+1], x[base+2], x[base+3]);
            y[base+0] = o.x; y[base+1] = o.y; y[base+2] = o.z; y[base+3] = o.w;
        }
    } else if (b == n_blocks) {
        const int colbase = n_blocks * BS;
        const int tail = row_len - colbase;
        int base = row0 * row_len + colbase;
        for (int row = row0; row < row1; ++row, base += row_len)
            for (int t = 0; t < tail; ++t)
                y[base + t] = (t < rem) ? x[base + t] * __ldg(dr + t) : 0.0f;
    }
}

extern "C" void kernel_launch(void* const* d_in, const int* in_sizes, int n_in,
                              void* d_out, int out_size)
{
    const float* x      = (const float*)d_in[0];
    const float* blocks = (const float*)d_in[1];
    const float* dr     = (const float*)d_in[2];
    float* y = (float*)d_out;

    const int n_blocks     = in_sizes[1] / (BS * BS);   // 1024
    const int rem          = in_sizes[2];               // 3
    const int block_region = n_blocks * BS;             // 4096
    const int row_len      = block_region + rem;        // 4099
    const int total_rows   = out_size / row_len;        // 16384

    if (n_blocks % GPC == 0 && (row_len & 3) == 3 && total_rows % RPC == 0) {
        const int gx = n_blocks / GPC;                              // 4
        const int gy = total_rows / RPC;                            // 1024
        dim3 grid(gx, gy, 1);
        block_apply_vec9_kernel<<<grid, GPC>>>(x, blocks, dr, y,
                                               n_blocks, rem, row_len, total_rows);
    } else {
        const int THREADS = 256;
        const int rows_per_cta = 8;
        dim3 grid((n_blocks + 1 + THREADS - 1) / THREADS,
                  (total_rows + rows_per_cta - 1) / rows_per_cta, 1);
        block_apply_simple_kernel<<<grid, THREADS>>>(x, blocks, dr, y,
                                                     n_blocks, rem, row_len,
                                                     total_rows, rows_per_cta);
    }
}

// round 15
// speedup vs baseline: 1.0541x; 1.0541x over previous
#include <cuda_runtime.h>
#include <cuda_bf16.h>

// y = D @ x per row, D = blockdiag(1024 x [4x4]) + diag(rem[3]).
// x: (16384, 4099) fp32. Row stride 4099 ≡ 3 (mod 4).
// Converged structure (R13): RPC=8, two static 4-row batches per CTA,
// 8192 CTAs, 64 regs, 4 CTAs/SM. Effective bandwidth ~6.96 TB/s (~98% of
// achievable mixed R/W ceiling). This revision only micro-trims issue slots.
//  * r pattern {0,3,2,1}: r=0 clean f4; r=2 direct 8B-aligned f2 (no shfl);
//    r=3 full shuffle path (6 shfl, f4 patch);
//    r=1 only 2 shuffles + scalar patch.

#define BS     4
#define GPC    256   // groups per CTA == blockDim.x
#define RPC    8     // rows per CTA (two static batches of 4)

struct W4 { float4 w0, w1, w2, w3; };

__device__ __forceinline__ float4 apply_w(const W4& w,
                                          float x0, float x1, float x2, float x3)
{
    float4 o;
    o.x = w.w0.x*x0 + w.w0.y*x1 + w.w0.z*x2 + w.w0.w*x3;
    o.y = w.w1.x*x0 + w.w1.y*x1 + w.w1.z*x2 + w.w1.w*x3;
    o.z = w.w2.x*x0 + w.w2.y*x1 + w.w2.z*x2 + w.w2.w*x3;
    o.w = w.w3.x*x0 + w.w3.y*x1 + w.w3.z*x2 + w.w3.w*x3;
    return o;
}

// R == 3 row: q at (s-3)+4*lane, p = lane31 patch quad x[(s-3)+128 ..].
__device__ __forceinline__ void process_row_r3(
    float4 q, float4 p, int s, int lane, const W4& w, float* __restrict__ y)
{
    float nx = __shfl_down_sync(0xffffffffu, q.x, 1);
    float ny = __shfl_down_sync(0xffffffffu, q.y, 1);
    float nz = __shfl_down_sync(0xffffffffu, q.z, 1);
    if (lane == 31) { nx = p.x; ny = p.y; nz = p.z; }

    float4 v = apply_w(w, q.w, nx, ny, nz);

    float p1 = __shfl_up_sync(0xffffffffu, v.y, 1);
    float p2 = __shfl_up_sync(0xffffffffu, v.z, 1);
    float p3 = __shfl_up_sync(0xffffffffu, v.w, 1);
    float4 o; o.x = p1; o.y = p2; o.z = p3; o.w = v.x;

    if (lane > 0) {
        __stcs(reinterpret_cast<float4*>(y + (s - 3)) + lane, o);
    } else {
        __stcs(y + s, v.x);
    }
    if (lane == 31) {
        __stcs(y + s + 125, v.y);
        __stcs(y + s + 126, v.z);
        __stcs(y + s + 127, v.w);
    }
}

// R == 1 row: q at (s-1)+4*lane, px = lane31 scalar patch x[s+127].
__device__ __forceinline__ void process_row_r1(
    float4 q, float px, int s, int lane, const W4& w, float* __restrict__ y)
{
    float nx = __shfl_down_sync(0xffffffffu, q.x, 1);
    if (lane == 31) nx = px;

    float4 v = apply_w(w, q.y, q.z, q.w, nx);

    float p3 = __shfl_up_sync(0xffffffffu, v.w, 1);
    float4 o; o.x = p3; o.y = v.x; o.z = v.y; o.w = v.z;

    if (lane > 0) {
        __stcs(reinterpret_cast<float4*>(y + (s - 1)) + lane, o);
    } else {
        __stcs(y + s + 0, v.x);
        __stcs(y + s + 1, v.y);
        __stcs(y + s + 2, v.z);
    }
    if (lane == 31) {
        __stcs(y + s + 127, v.w);
    }
}

// One static 4-row batch starting at flat offset s0 (s0 % 4 == 0).
// r per row: {0, 3, 2, 1}.
__device__ __forceinline__ void process_batch4(
    const float* __restrict__ x, float* __restrict__ y,
    int s0, int row_len, int lane, const W4& w)
{
    const int rl2 = 2 * row_len;
    const int rl3 = 3 * row_len;

    const float4* a0 = reinterpret_cast<const float4*>(x + s0);
    const float4* a1 = reinterpret_cast<const float4*>(x + s0 + row_len - 3);
    const float2* a2 = reinterpret_cast<const float2*>(x + s0 + rl2 + 4 * lane);
    const float4* a3 = reinterpret_cast<const float4*>(x + s0 + rl3 - 1);

    // ---- load phase: all rows in flight before compute ----
    float4 q0 = __ldcs(a0 + lane);
    float4 q1 = __ldcs(a1 + lane);
    float2 q2l = __ldcs(a2 + 0);
    float2 q2h = __ldcs(a2 + 1);
    float4 q3 = __ldcs(a3 + lane);
    float4 p1 = {0,0,0,0};
    float  p3x = 0.0f;
    if (lane == 31) {
        p1  = __ldg(a1 + 32);                   // f4 patch (x,y,z used)
        p3x = __ldg(x + s0 + rl3 + 127);        // scalar patch for r=1 row
    }

    // row +0 (r=0): clean float4
    {
        float4 o = apply_w(w, q0.x, q0.y, q0.z, q0.w);
        __stcs(reinterpret_cast<float4*>(y + s0) + lane, o);
    }
    // row +1 (r=3)
    process_row_r3(q1, p1, s0 + row_len, lane, w, y);
    // row +2 (r=2): direct 8B-aligned float2 path
    {
        float4 o = apply_w(w, q2l.x, q2l.y, q2h.x, q2h.y);
        float2* ob = reinterpret_cast<float2*>(y + s0 + rl2 + 4 * lane);
        __stcs(ob + 0, make_float2(o.x, o.y));
        __stcs(ob + 1, make_float2(o.z, o.w));
    }
    // row +3 (r=1)
    process_row_r1(q3, p3x, s0 + rl3, lane, w, y);
}

__global__ void __launch_bounds__(256, 4) block_apply_vec10_kernel(
    const float* __restrict__ x,
    const float* __restrict__ blocks,
    const float* __restrict__ dr,
    float* __restrict__ y,
    int n_blocks, int rem, int row_len, int total_rows)
{
    const int tid  = threadIdx.x;
    const int lane = tid & 31;
    const int g    = blockIdx.x * GPC + tid;

    W4 w;
    {
        const float4* bp = reinterpret_cast<const float4*>(blocks) + g * BS;
        w.w0 = __ldg(bp + 0); w.w1 = __ldg(bp + 1);
        w.w2 = __ldg(bp + 2); w.w3 = __ldg(bp + 3);
    }

    const int row0 = blockIdx.y * RPC;                    // multiple of 4
    const int warp_col0 = blockIdx.x * (GPC * BS) + (tid & ~31) * BS;

    if (row0 + RPC <= total_rows) {
        const int s0 = row0 * row_len + warp_col0;        // s0 % 4 == 0
        process_batch4(x, y, s0, row_len, lane, w);
        process_batch4(x, y, s0 + 4 * row_len, row_len, lane, w);
    } else {
        // generic tail rows: scalar per-group path
        for (int row = row0; row < total_rows; ++row) {
            int base = row * row_len + g * BS;
            float4 o = apply_w(w, x[base+0], x[base+1], x[base+2], x[base+3]);
            y[base+0] = o.x; y[base+1] = o.y; y[base+2] = o.z; y[base+3] = o.w;
        }
    }

    // fused remainder duty: last column-CTA handles the diagonal tail
    if (blockIdx.x == gridDim.x - 1) {
        const int colbase = n_blocks * BS;
        const int tail = row_len - colbase;                 // == rem here
        const int row1 = min(row0 + RPC, total_rows);
        // strength-reduced: thread t covers (row, k) pairs without divides
        if (tid < tail * (row1 - row0)) {
            int rr = 0, k = tid;
            while (k >= tail) { k -= tail; ++rr; }          // <=7 iters, tiny
            int idx = (row0 + rr) * row_len + colbase + k;
            y[idx] = (k < rem) ? x[idx] * __ldg(dr + k) : 0.0f;
        }
    }
}

// Fallback for general shapes: thread owns a block, scalar path.
__global__ void __launch_bounds__(256) block_apply_simple_kernel(
    const float* __restrict__ x, const float* __restrict__ blocks,
    const float* __restrict__ dr, float* __restrict__ y,
    int n_blocks, int rem, int row_len, int total_rows, int rows_per_cta)
{
    const int b = blockIdx.x * blockDim.x + threadIdx.x;
    int row0 = blockIdx.y * rows_per_cta;
    int row1 = min(row0 + rows_per_cta, total_rows);
    if (b < n_blocks) {
        const float4* bp = reinterpret_cast<const float4*>(blocks) + b * BS;
        W4 w; w.w0 = __ldg(bp+0); w.w1 = __ldg(bp+1);
              w.w2 = __ldg(bp+2); w.w3 = __ldg(bp+3);
        int base = row0 * row_len + b * BS;
        for (int row = row0; row < row1; ++row, base += row_len) {
            float4 o = apply_w(w, x[base+0], x[base+1], x[base+2], x[base+3]);
            y[base+0] = o.x; y[base+1] = o.y; y[base+2] = o.z; y[base+3] = o.w;
        }
    } else if (b == n_blocks) {
        const int colbase = n_blocks * BS;
        const int tail = row_len - colbase;
        int base = row0 * row_len + colbase;
        for (int row = row0; row < row1; ++row, base += row_len)
            for (int t = 0; t < tail; ++t)
                y[base + t] = (t < rem) ? x[base + t] * __ldg(dr + t) : 0.0f;
    }
}

extern "C" void kernel_launch(void* const* d_in, const int* in_sizes, int n_in,
                              void* d_out, int out_size)
{
    const float* x      = (const float*)d_in[0];
    const float* blocks = (const float*)d_in[1];
    const float* dr     = (const float*)d_in[2];
    float* y = (float*)d_out;

    const int n_blocks     = in_sizes[1] / (BS * BS);   // 1024
    const int rem          = in_sizes[2];               // 3
    const int block_region = n_blocks * BS;             // 4096
    const int row_len      = block_region + rem;        // 4099
    const int total_rows   = out_size / row_len;        // 16384

    if (n_blocks % GPC == 0 && (row_len & 3) == 3 &&
        (row_len - block_region) * RPC <= GPC) {
        const int gx = n_blocks / GPC;                              // 4
        const int gy = (total_rows + RPC - 1) / RPC;                // 2048
        dim3 grid(gx, gy, 1);
        block_apply_vec10_kernel<<<grid, GPC>>>(x, blocks, dr, y,
                                                n_blocks, rem, row_len, total_rows);
    } else {
        const int THREADS = 256;
        const int rows_per_cta = 8;
        dim3 grid((n_blocks + 1 + THREADS - 1) / THREADS,
                  (total_rows + rows_per_cta - 1) / rows_per_cta, 1);
        block_apply_simple_kernel<<<grid, THREADS>>>(x, blocks, dr, y,
                                                     n_blocks, rem, row_len,
                                                     total_rows, rows_per_cta);
    }
}